// round 4
// baseline (speedup 1.0000x reference)
#include <cuda_runtime.h>

#define LSEQ 2048
#define BB 2
#define HIDD 1024
#define HEADS 16
#define DH 64
#define NTOK (LSEQ*BB)

// ---------------- scratch (device globals; no allocation allowed) ----------------
__device__ float g_Q[(size_t)BB*HEADS*LSEQ*DH];
__device__ float g_K[(size_t)BB*HEADS*LSEQ*DH];
__device__ float g_V[(size_t)BB*HEADS*LSEQ*DH];
__device__ float g_ctx[(size_t)NTOK*HIDD];
__device__ float g_mb[BB*LSEQ];

// ---------------- mask normalization (dtype-robust) ----------------
// mask may arrive as bool (1B), int32 (4B) or float32 (4B). Values are only 0/1.
//  - any byte > 1            -> float32 storage (e.g. 1.0f has bytes 0x80,0x3f)
//  - any nonzero byte at i%4!=0 (values 0/1 only) -> 1-byte bool storage
//  - else                    -> int32 little-endian storage
__global__ void prep_mask(const unsigned char* __restrict__ mraw) {
    __shared__ int s_u8, s_f32;
    int t = threadIdx.x;
    if (t == 0) { s_u8 = 0; s_f32 = 0; }
    __syncthreads();
    int u8 = 0, f32 = 0;
    for (int i = t; i < BB*LSEQ; i += blockDim.x) {
        unsigned char v = mraw[i];
        if (v > 1) f32 = 1;
        if ((i & 3) != 0 && v) u8 = 1;
    }
    if (u8)  atomicOr(&s_u8, 1);
    if (f32) atomicOr(&s_f32, 1);
    __syncthreads();
    int is_f32 = s_f32, is_u8 = s_u8;
    for (int i = t; i < BB*LSEQ; i += blockDim.x) {
        bool m;
        if (is_f32)      m = (((const float*)mraw)[i] != 0.0f);
        else if (is_u8)  m = (mraw[i] != 0);
        else             m = (((const int*)mraw)[i] != 0);
        g_mb[i] = m ? -1e30f : 0.0f;
    }
}

// ---------------- GEMM: Y = X @ W^T + bias ----------------
// X: [NTOK, HIDD] row-major (row r = l*B + b), W: [out, in] row-major.
// omode 0/1/2 : scatter into g_Q/g_K/g_V with layout [b][h][l][d]
// omode 3     : plain [r][o] into Yext (used for final FC -> d_out)
// xsel 1      : X taken from g_ctx (device global) instead of param.
__global__ __launch_bounds__(256) void gemm_wt(
    const float* __restrict__ Xp, const float* __restrict__ W,
    const float* __restrict__ bias, float* __restrict__ Yext,
    int xsel, int omode)
{
    const float* X = xsel ? g_ctx : Xp;
    __shared__ float As[16][128];
    __shared__ float Bs[16][128];
    int tid = threadIdx.x;
    int m0 = blockIdx.y * 128, n0 = blockIdx.x * 128;
    int tx = tid & 15, ty = tid >> 4;

    float acc[8][8];
#pragma unroll
    for (int i = 0; i < 8; i++)
#pragma unroll
        for (int j = 0; j < 8; j++) acc[i][j] = 0.0f;

    for (int kt = 0; kt < HIDD; kt += 16) {
#pragma unroll
        for (int i = tid; i < 512; i += 256) {
            int row = i >> 2, c4 = (i & 3) << 2;
            float4 a = *(const float4*)(X + (size_t)(m0 + row) * HIDD + kt + c4);
            As[c4 + 0][row] = a.x; As[c4 + 1][row] = a.y;
            As[c4 + 2][row] = a.z; As[c4 + 3][row] = a.w;
            float4 b = *(const float4*)(W + (size_t)(n0 + row) * HIDD + kt + c4);
            Bs[c4 + 0][row] = b.x; Bs[c4 + 1][row] = b.y;
            Bs[c4 + 2][row] = b.z; Bs[c4 + 3][row] = b.w;
        }
        __syncthreads();
#pragma unroll
        for (int k = 0; k < 16; k++) {
            float4 a0 = *(const float4*)&As[k][ty * 8];
            float4 a1 = *(const float4*)&As[k][ty * 8 + 4];
            float4 b0 = *(const float4*)&Bs[k][tx * 8];
            float4 b1 = *(const float4*)&Bs[k][tx * 8 + 4];
            float av[8] = {a0.x, a0.y, a0.z, a0.w, a1.x, a1.y, a1.z, a1.w};
            float bv[8] = {b0.x, b0.y, b0.z, b0.w, b1.x, b1.y, b1.z, b1.w};
#pragma unroll
            for (int i = 0; i < 8; i++)
#pragma unroll
                for (int j = 0; j < 8; j++) acc[i][j] += av[i] * bv[j];
        }
        __syncthreads();
    }

    if (omode == 3) {
#pragma unroll
        for (int i = 0; i < 8; i++) {
            int r = m0 + ty * 8 + i;
#pragma unroll
            for (int j = 0; j < 8; j++) {
                int o = n0 + tx * 8 + j;
                Yext[(size_t)r * HIDD + o] = acc[i][j] + bias[o];
            }
        }
    } else {
        float* dst = (omode == 0) ? g_Q : (omode == 1) ? g_K : g_V;
#pragma unroll
        for (int i = 0; i < 8; i++) {
            int r = m0 + ty * 8 + i;
            int l = r >> 1, bb = r & 1;           // r = l*B + b, B=2
#pragma unroll
            for (int j = 0; j < 8; j++) {
                int o = n0 + tx * 8 + j;
                int h = o >> 6, d = o & 63;
                dst[(((size_t)(bb * HEADS + h)) * LSEQ + l) * DH + d] = acc[i][j] + bias[o];
            }
        }
    }
}

// ---------------- flash attention, fp32, 64q x 64k tiles ----------------
// 256 threads = 16x16 grid: ty -> 4 query rows, tx -> 4 key cols (S phase)
// and tx -> 4 output dims (PV phase). Smem layouts chosen so all LDS.128
// are conflict-free or broadcast.
#define SPITCH 68
__global__ __launch_bounds__(256) void attn_kernel(const float* __restrict__ tao) {
    extern __shared__ float sm[];
    float* Qt = sm;                      // [DH][SPITCH] transposed, pre-scaled
    float* Kt = Qt + 64 * SPITCH;        // [DH][SPITCH] transposed
    float* Vs = Kt + 64 * SPITCH;        // [64k][SPITCH]
    float* Ps = Vs + 64 * SPITCH;        // [64q][SPITCH]

    int bh = blockIdx.x;
    int b = bh >> 4, h = bh & 15;
    int q0 = blockIdx.y * 64;
    int tid = threadIdx.x;
    int tx = tid & 15, ty = tid >> 4;
    int qy = ty * 4, kx = tx * 4;        // kx doubles as dx in PV phase

    float tt = tao[h];
    float nh = -0.5f / (tt * tt * tt * tt);
    const float SCALE = 0.125f;          // DH^-0.5

    size_t base = ((size_t)(b * HEADS + h)) * LSEQ * DH;

    // load Q tile transposed + pre-scaled
    for (int i = tid; i < 1024; i += 256) {
        int r = i >> 4, d0 = (i & 15) << 2;
        float4 v = *(const float4*)(g_Q + base + (size_t)(q0 + r) * DH + d0);
        Qt[(d0 + 0) * SPITCH + r] = v.x * SCALE;
        Qt[(d0 + 1) * SPITCH + r] = v.y * SCALE;
        Qt[(d0 + 2) * SPITCH + r] = v.z * SCALE;
        Qt[(d0 + 3) * SPITCH + r] = v.w * SCALE;
    }

    float m[4], l[4], acc[4][4];
#pragma unroll
    for (int i = 0; i < 4; i++) {
        m[i] = -3.0e38f; l[i] = 0.0f;
#pragma unroll
        for (int j = 0; j < 4; j++) acc[i][j] = 0.0f;
    }

    for (int k0 = 0; k0 < LSEQ; k0 += 64) {
        __syncthreads();   // previous tile's Ps/Vs readers done (also covers Qt on iter 0)
        for (int i = tid; i < 1024; i += 256) {
            int r = i >> 4, d0 = (i & 15) << 2;
            float4 kv = *(const float4*)(g_K + base + (size_t)(k0 + r) * DH + d0);
            Kt[(d0 + 0) * SPITCH + r] = kv.x;
            Kt[(d0 + 1) * SPITCH + r] = kv.y;
            Kt[(d0 + 2) * SPITCH + r] = kv.z;
            Kt[(d0 + 3) * SPITCH + r] = kv.w;
            float4 vv = *(const float4*)(g_V + base + (size_t)(k0 + r) * DH + d0);
            *(float4*)&Vs[r * SPITCH + d0] = vv;
        }
        __syncthreads();

        // S = (Q*scale) @ K^T  (outer-product over d)
        float s[4][4];
#pragma unroll
        for (int i = 0; i < 4; i++)
#pragma unroll
            for (int j = 0; j < 4; j++) s[i][j] = 0.0f;
#pragma unroll 8
        for (int d = 0; d < 64; d++) {
            float4 qv = *(const float4*)&Qt[d * SPITCH + qy];
            float4 kv = *(const float4*)&Kt[d * SPITCH + kx];
            float qa[4] = {qv.x, qv.y, qv.z, qv.w};
            float ka[4] = {kv.x, kv.y, kv.z, kv.w};
#pragma unroll
            for (int i = 0; i < 4; i++)
#pragma unroll
                for (int j = 0; j < 4; j++) s[i][j] += qa[i] * ka[j];
        }

        // gaussian positional bias + key mask
        float mbj[4];
#pragma unroll
        for (int j = 0; j < 4; j++) mbj[j] = g_mb[b * LSEQ + k0 + kx + j];
#pragma unroll
        for (int i = 0; i < 4; i++) {
            int qg = q0 + qy + i;
#pragma unroll
            for (int j = 0; j < 4; j++) {
                float diff = (float)(qg - (k0 + kx + j));
                s[i][j] += diff * diff * nh + mbj[j];
            }
        }

        // online softmax update (row reductions across the 16 tx lanes)
#pragma unroll
        for (int i = 0; i < 4; i++) {
            float mt = fmaxf(fmaxf(s[i][0], s[i][1]), fmaxf(s[i][2], s[i][3]));
#pragma unroll
            for (int o = 1; o < 16; o <<= 1)
                mt = fmaxf(mt, __shfl_xor_sync(0xffffffffu, mt, o));
            float mn = fmaxf(m[i], mt);
            float c = __expf(m[i] - mn);
            float rs = 0.0f;
#pragma unroll
            for (int j = 0; j < 4; j++) {
                s[i][j] = __expf(s[i][j] - mn);
                rs += s[i][j];
            }
#pragma unroll
            for (int o = 1; o < 16; o <<= 1)
                rs += __shfl_xor_sync(0xffffffffu, rs, o);
            l[i] = l[i] * c + rs;
            m[i] = mn;
#pragma unroll
            for (int j = 0; j < 4; j++) {
                acc[i][j] *= c;
                Ps[(qy + i) * SPITCH + kx + j] = s[i][j];
            }
        }
        __syncthreads();

        // acc += P @ V
#pragma unroll 8
        for (int k = 0; k < 64; k++) {
            float4 vv = *(const float4*)&Vs[k * SPITCH + kx];
            float va[4] = {vv.x, vv.y, vv.z, vv.w};
#pragma unroll
            for (int i = 0; i < 4; i++) {
                float p = Ps[(qy + i) * SPITCH + k];
#pragma unroll
                for (int j = 0; j < 4; j++) acc[i][j] += p * va[j];
            }
        }
    }

    // write context: row r = q*B + b, col = h*64 + d
#pragma unroll
    for (int i = 0; i < 4; i++) {
        float inv = 1.0f / l[i];
        int qg = q0 + qy + i;
#pragma unroll
        for (int j = 0; j < 4; j++)
            g_ctx[((size_t)qg * BB + b) * HIDD + h * DH + kx + j] = acc[i][j] * inv;
    }
}

// ---------------- launcher ----------------
// Inputs are classified by element count (robust to metadata ordering):
//   L*B*HID = 4194304 -> activations (q, k, v in order of appearance)
//   HID*HID = 1048576 -> weights     (wq, wk, wv, wfc in order)
//   B*L     =    4096 -> mask
//   HID     =    1024 -> biases      (bq, bk, bv, bfc in order)
//   HEADS   =      16 -> tao
extern "C" void kernel_launch(void* const* d_in, const int* in_sizes, int n_in,
                              void* d_out, int out_size) {
    const float* act[3] = {nullptr, nullptr, nullptr};
    const float* W[4]   = {nullptr, nullptr, nullptr, nullptr};
    const float* Bv[4]  = {nullptr, nullptr, nullptr, nullptr};
    const float* tao = nullptr;
    const unsigned char* mask = nullptr;
    int na = 0, nw = 0, nb = 0;
    for (int i = 0; i < n_in; i++) {
        long s = in_sizes[i];
        if (s == (long)LSEQ * BB * HIDD)      { if (na < 3) act[na++] = (const float*)d_in[i]; }
        else if (s == (long)HIDD * HIDD)      { if (nw < 4) W[nw++]   = (const float*)d_in[i]; }
        else if (s == (long)HIDD)             { if (nb < 4) Bv[nb++]  = (const float*)d_in[i]; }
        else if (s == (long)HEADS)            { tao = (const float*)d_in[i]; }
        else if (s == (long)BB * LSEQ)        { mask = (const unsigned char*)d_in[i]; }
    }
    float* out = (float*)d_out;

    prep_mask<<<1, 1024>>>(mask);

    dim3 gg(HIDD / 128, NTOK / 128);
    gemm_wt<<<gg, 256>>>(act[0], W[0], Bv[0], nullptr, 0, 0);   // Q = q @ wq^T + bq
    gemm_wt<<<gg, 256>>>(act[1], W[1], Bv[1], nullptr, 0, 1);   // K = k @ wk^T + bk
    gemm_wt<<<gg, 256>>>(act[2], W[2], Bv[2], nullptr, 0, 2);   // V = v @ wv^T + bv

    const int SMEM = 4 * 64 * SPITCH * (int)sizeof(float);   // 69632 B
    cudaFuncSetAttribute(attn_kernel, cudaFuncAttributeMaxDynamicSharedMemorySize, SMEM);
    attn_kernel<<<dim3(BB * HEADS, LSEQ / 64), 256, SMEM>>>(tao);

    gemm_wt<<<gg, 256>>>(nullptr, W[3], Bv[3], out, 1, 3);      // out = ctx @ wfc^T + bfc
}

// round 5
// speedup vs baseline: 1.0001x; 1.0001x over previous
#include <cuda_runtime.h>

#define LSEQ 2048
#define BB 2
#define HIDD 1024
#define HEADS 16
#define DH 64
#define NTOK (LSEQ*BB)

// ---------------- scratch (device globals; no allocation allowed) ----------------
__device__ float g_Q[(size_t)BB*HEADS*LSEQ*DH];
__device__ float g_K[(size_t)BB*HEADS*LSEQ*DH];
__device__ float g_V[(size_t)BB*HEADS*LSEQ*DH];
__device__ float g_ctx[(size_t)NTOK*HIDD];
__device__ float g_mb[BB*LSEQ];

// ---------------- mask normalization (dtype-robust) ----------------
// mask may arrive as bool (1B), int32 (4B) or float32 (4B). Values are only 0/1.
//  - any byte > 1            -> float32 storage (e.g. 1.0f has bytes 0x80,0x3f)
//  - any nonzero byte at i%4!=0 (values 0/1 only) -> 1-byte bool storage
//  - else                    -> int32 little-endian storage
__global__ void prep_mask(const unsigned char* __restrict__ mraw) {
    __shared__ int s_u8, s_f32;
    int t = threadIdx.x;
    if (t == 0) { s_u8 = 0; s_f32 = 0; }
    __syncthreads();
    int u8 = 0, f32 = 0;
    for (int i = t; i < BB*LSEQ; i += blockDim.x) {
        unsigned char v = mraw[i];
        if (v > 1) f32 = 1;
        if ((i & 3) != 0 && v) u8 = 1;
    }
    if (u8)  atomicOr(&s_u8, 1);
    if (f32) atomicOr(&s_f32, 1);
    __syncthreads();
    int is_f32 = s_f32, is_u8 = s_u8;
    for (int i = t; i < BB*LSEQ; i += blockDim.x) {
        bool m;
        if (is_f32)      m = (((const float*)mraw)[i] != 0.0f);
        else if (is_u8)  m = (mraw[i] != 0);
        else             m = (((const int*)mraw)[i] != 0);
        g_mb[i] = m ? -1e30f : 0.0f;
    }
}

// ---------------- GEMM: Y = X @ W^T + bias ----------------
// X: [NTOK, HIDD] row-major (row r = l*B + b), W: [out, in] row-major.
// omode 0/1/2 : scatter into g_Q/g_K/g_V with layout [b][h][l][d]
// omode 3     : plain [r][o] into Yext (used for final FC -> d_out)
// xsel 1      : X taken from g_ctx (device global) instead of param.
__global__ __launch_bounds__(256) void gemm_wt(
    const float* __restrict__ Xp, const float* __restrict__ W,
    const float* __restrict__ bias, float* __restrict__ Yext,
    int xsel, int omode)
{
    const float* X = xsel ? g_ctx : Xp;
    __shared__ float As[16][128];
    __shared__ float Bs[16][128];
    int tid = threadIdx.x;
    int m0 = blockIdx.y * 128, n0 = blockIdx.x * 128;
    int tx = tid & 15, ty = tid >> 4;

    float acc[8][8];
#pragma unroll
    for (int i = 0; i < 8; i++)
#pragma unroll
        for (int j = 0; j < 8; j++) acc[i][j] = 0.0f;

    for (int kt = 0; kt < HIDD; kt += 16) {
#pragma unroll
        for (int i = tid; i < 512; i += 256) {
            int row = i >> 2, c4 = (i & 3) << 2;
            float4 a = *(const float4*)(X + (size_t)(m0 + row) * HIDD + kt + c4);
            As[c4 + 0][row] = a.x; As[c4 + 1][row] = a.y;
            As[c4 + 2][row] = a.z; As[c4 + 3][row] = a.w;
            float4 b = *(const float4*)(W + (size_t)(n0 + row) * HIDD + kt + c4);
            Bs[c4 + 0][row] = b.x; Bs[c4 + 1][row] = b.y;
            Bs[c4 + 2][row] = b.z; Bs[c4 + 3][row] = b.w;
        }
        __syncthreads();
#pragma unroll
        for (int k = 0; k < 16; k++) {
            float4 a0 = *(const float4*)&As[k][ty * 8];
            float4 a1 = *(const float4*)&As[k][ty * 8 + 4];
            float4 b0 = *(const float4*)&Bs[k][tx * 8];
            float4 b1 = *(const float4*)&Bs[k][tx * 8 + 4];
            float av[8] = {a0.x, a0.y, a0.z, a0.w, a1.x, a1.y, a1.z, a1.w};
            float bv[8] = {b0.x, b0.y, b0.z, b0.w, b1.x, b1.y, b1.z, b1.w};
#pragma unroll
            for (int i = 0; i < 8; i++)
#pragma unroll
                for (int j = 0; j < 8; j++) acc[i][j] += av[i] * bv[j];
        }
        __syncthreads();
    }

    if (omode == 3) {
#pragma unroll
        for (int i = 0; i < 8; i++) {
            int r = m0 + ty * 8 + i;
#pragma unroll
            for (int j = 0; j < 8; j++) {
                int o = n0 + tx * 8 + j;
                Yext[(size_t)r * HIDD + o] = acc[i][j] + bias[o];
            }
        }
    } else {
        float* dst = (omode == 0) ? g_Q : (omode == 1) ? g_K : g_V;
#pragma unroll
        for (int i = 0; i < 8; i++) {
            int r = m0 + ty * 8 + i;
            int l = r >> 1, bb = r & 1;           // r = l*B + b, B=2
#pragma unroll
            for (int j = 0; j < 8; j++) {
                int o = n0 + tx * 8 + j;
                int h = o >> 6, d = o & 63;
                dst[(((size_t)(bb * HEADS + h)) * LSEQ + l) * DH + d] = acc[i][j] + bias[o];
            }
        }
    }
}

// ---------------- flash attention, fp32, 64q x 64k tiles ----------------
// 256 threads = 16x16 grid: ty -> 4 query rows, tx -> 4 key cols (S phase)
// and tx -> 4 output dims (PV phase). Smem layouts chosen so all LDS.128
// are conflict-free or broadcast.
#define SPITCH 68
__global__ __launch_bounds__(256) void attn_kernel(const float* __restrict__ tao) {
    extern __shared__ float sm[];
    float* Qt = sm;                      // [DH][SPITCH] transposed, pre-scaled
    float* Kt = Qt + 64 * SPITCH;        // [DH][SPITCH] transposed
    float* Vs = Kt + 64 * SPITCH;        // [64k][SPITCH]
    float* Ps = Vs + 64 * SPITCH;        // [64q][SPITCH]

    int bh = blockIdx.x;
    int b = bh >> 4, h = bh & 15;
    int q0 = blockIdx.y * 64;
    int tid = threadIdx.x;
    int tx = tid & 15, ty = tid >> 4;
    int qy = ty * 4, kx = tx * 4;        // kx doubles as dx in PV phase

    float tt = tao[h];
    float nh = -0.5f / (tt * tt * tt * tt);
    const float SCALE = 0.125f;          // DH^-0.5

    size_t base = ((size_t)(b * HEADS + h)) * LSEQ * DH;

    // load Q tile transposed + pre-scaled
    for (int i = tid; i < 1024; i += 256) {
        int r = i >> 4, d0 = (i & 15) << 2;
        float4 v = *(const float4*)(g_Q + base + (size_t)(q0 + r) * DH + d0);
        Qt[(d0 + 0) * SPITCH + r] = v.x * SCALE;
        Qt[(d0 + 1) * SPITCH + r] = v.y * SCALE;
        Qt[(d0 + 2) * SPITCH + r] = v.z * SCALE;
        Qt[(d0 + 3) * SPITCH + r] = v.w * SCALE;
    }

    float m[4], l[4], acc[4][4];
#pragma unroll
    for (int i = 0; i < 4; i++) {
        m[i] = -3.0e38f; l[i] = 0.0f;
#pragma unroll
        for (int j = 0; j < 4; j++) acc[i][j] = 0.0f;
    }

    for (int k0 = 0; k0 < LSEQ; k0 += 64) {
        __syncthreads();   // previous tile's Ps/Vs readers done (also covers Qt on iter 0)
        for (int i = tid; i < 1024; i += 256) {
            int r = i >> 4, d0 = (i & 15) << 2;
            float4 kv = *(const float4*)(g_K + base + (size_t)(k0 + r) * DH + d0);
            Kt[(d0 + 0) * SPITCH + r] = kv.x;
            Kt[(d0 + 1) * SPITCH + r] = kv.y;
            Kt[(d0 + 2) * SPITCH + r] = kv.z;
            Kt[(d0 + 3) * SPITCH + r] = kv.w;
            float4 vv = *(const float4*)(g_V + base + (size_t)(k0 + r) * DH + d0);
            *(float4*)&Vs[r * SPITCH + d0] = vv;
        }
        __syncthreads();

        // S = (Q*scale) @ K^T  (outer-product over d)
        float s[4][4];
#pragma unroll
        for (int i = 0; i < 4; i++)
#pragma unroll
            for (int j = 0; j < 4; j++) s[i][j] = 0.0f;
#pragma unroll 8
        for (int d = 0; d < 64; d++) {
            float4 qv = *(const float4*)&Qt[d * SPITCH + qy];
            float4 kv = *(const float4*)&Kt[d * SPITCH + kx];
            float qa[4] = {qv.x, qv.y, qv.z, qv.w};
            float ka[4] = {kv.x, kv.y, kv.z, kv.w};
#pragma unroll
            for (int i = 0; i < 4; i++)
#pragma unroll
                for (int j = 0; j < 4; j++) s[i][j] += qa[i] * ka[j];
        }

        // gaussian positional bias + key mask
        float mbj[4];
#pragma unroll
        for (int j = 0; j < 4; j++) mbj[j] = g_mb[b * LSEQ + k0 + kx + j];
#pragma unroll
        for (int i = 0; i < 4; i++) {
            int qg = q0 + qy + i;
#pragma unroll
            for (int j = 0; j < 4; j++) {
                float diff = (float)(qg - (k0 + kx + j));
                s[i][j] += diff * diff * nh + mbj[j];
            }
        }

        // online softmax update (row reductions across the 16 tx lanes)
#pragma unroll
        for (int i = 0; i < 4; i++) {
            float mt = fmaxf(fmaxf(s[i][0], s[i][1]), fmaxf(s[i][2], s[i][3]));
#pragma unroll
            for (int o = 1; o < 16; o <<= 1)
                mt = fmaxf(mt, __shfl_xor_sync(0xffffffffu, mt, o));
            float mn = fmaxf(m[i], mt);
            float c = __expf(m[i] - mn);
            float rs = 0.0f;
#pragma unroll
            for (int j = 0; j < 4; j++) {
                s[i][j] = __expf(s[i][j] - mn);
                rs += s[i][j];
            }
#pragma unroll
            for (int o = 1; o < 16; o <<= 1)
                rs += __shfl_xor_sync(0xffffffffu, rs, o);
            l[i] = l[i] * c + rs;
            m[i] = mn;
#pragma unroll
            for (int j = 0; j < 4; j++) {
                acc[i][j] *= c;
                Ps[(qy + i) * SPITCH + kx + j] = s[i][j];
            }
        }
        __syncthreads();

        // acc += P @ V
#pragma unroll 8
        for (int k = 0; k < 64; k++) {
            float4 vv = *(const float4*)&Vs[k * SPITCH + kx];
            float va[4] = {vv.x, vv.y, vv.z, vv.w};
#pragma unroll
            for (int i = 0; i < 4; i++) {
                float p = Ps[(qy + i) * SPITCH + k];
#pragma unroll
                for (int j = 0; j < 4; j++) acc[i][j] += p * va[j];
            }
        }
    }

    // write context: row r = q*B + b, col = h*64 + d
#pragma unroll
    for (int i = 0; i < 4; i++) {
        float inv = 1.0f / l[i];
        int qg = q0 + qy + i;
#pragma unroll
        for (int j = 0; j < 4; j++)
            g_ctx[((size_t)qg * BB + b) * HIDD + h * DH + kx + j] = acc[i][j] * inv;
    }
}

// ---------------- launcher ----------------
// Inputs are classified by element count (robust to metadata ordering):
//   L*B*HID = 4194304 -> activations (q, k, v in order of appearance)
//   HID*HID = 1048576 -> weights     (wq, wk, wv, wfc in order)
//   B*L     =    4096 -> mask
//   HID     =    1024 -> biases      (bq, bk, bv, bfc in order)
//   HEADS   =      16 -> tao
extern "C" void kernel_launch(void* const* d_in, const int* in_sizes, int n_in,
                              void* d_out, int out_size) {
    const float* act[3] = {nullptr, nullptr, nullptr};
    const float* W[4]   = {nullptr, nullptr, nullptr, nullptr};
    const float* Bv[4]  = {nullptr, nullptr, nullptr, nullptr};
    const float* tao = nullptr;
    const unsigned char* mask = nullptr;
    int na = 0, nw = 0, nb = 0;
    for (int i = 0; i < n_in; i++) {
        long s = in_sizes[i];
        if (s == (long)LSEQ * BB * HIDD)      { if (na < 3) act[na++] = (const float*)d_in[i]; }
        else if (s == (long)HIDD * HIDD)      { if (nw < 4) W[nw++]   = (const float*)d_in[i]; }
        else if (s == (long)HIDD)             { if (nb < 4) Bv[nb++]  = (const float*)d_in[i]; }
        else if (s == (long)HEADS)            { tao = (const float*)d_in[i]; }
        else if (s == (long)BB * LSEQ)        { mask = (const unsigned char*)d_in[i]; }
    }
    float* out = (float*)d_out;

    prep_mask<<<1, 1024>>>(mask);

    dim3 gg(HIDD / 128, NTOK / 128);
    gemm_wt<<<gg, 256>>>(act[0], W[0], Bv[0], nullptr, 0, 0);   // Q = q @ wq^T + bq
    gemm_wt<<<gg, 256>>>(act[1], W[1], Bv[1], nullptr, 0, 1);   // K = k @ wk^T + bk
    gemm_wt<<<gg, 256>>>(act[2], W[2], Bv[2], nullptr, 0, 2);   // V = v @ wv^T + bv

    const int SMEM = 4 * 64 * SPITCH * (int)sizeof(float);   // 69632 B
    cudaFuncSetAttribute(attn_kernel, cudaFuncAttributeMaxDynamicSharedMemorySize, SMEM);
    attn_kernel<<<dim3(BB * HEADS, LSEQ / 64), 256, SMEM>>>(tao);

    gemm_wt<<<gg, 256>>>(nullptr, W[3], Bv[3], out, 1, 3);      // out = ctx @ wfc^T + bfc
}